// round 3
// baseline (speedup 1.0000x reference)
#include <cuda_runtime.h>

#define N_NODES 100000
#define N_EDGES 1600000
#define D 128
#define F4 32          // float4 per row
#define D_OUT 64
#define BN_EPS 1e-5f

// ---------------- static device scratch (no allocations allowed) ----------------
__device__ int g_cnt[N_NODES];
__device__ int g_rowptr[N_NODES + 1];
__device__ int g_fill[N_NODES];
__device__ int g_col[N_EDGES];
__device__ float4 g_h[N_NODES * F4];     // current node features (post-layer)
__device__ float4 g_tmp[N_NODES * F4];   // pre-BN combined features (incl. readout)
__device__ __align__(16) float g_sum[3][D];
__device__ __align__(16) float g_sq[3][D];
__device__ __align__(16) float g_ro[3][D];      // readout per layer (colsum of h fed into layer)
__device__ __align__(16) float g_scale[3][D];   // gamma * rsqrt(var+eps)
__device__ __align__(16) float g_mean[3][D];    // mean of stored tmp values (incl. readout)
__device__ __align__(16) float g_beta[3][D];

// ---------------- init ----------------
__global__ void zero_kernel() {
    int i = blockIdx.x * 256 + threadIdx.x;
    if (i < N_NODES) g_cnt[i] = 0;
    if (i < 3 * D) {
        (&g_sum[0][0])[i] = 0.f;
        (&g_sq[0][0])[i]  = 0.f;
        (&g_ro[0][0])[i]  = 0.f;
    }
}

// ---------------- CSR build (edge_index delivered as int32 by the harness) ----------------
__global__ void hist_kernel(const int* __restrict__ ei) {
    int e = blockIdx.x * 256 + threadIdx.x;
    if (e < N_EDGES) {
        int d = ei[e];                      // dst = edge_index[0][e]
        atomicAdd(&g_cnt[d], 1);
    }
}

// single-block scan, 1024 threads x 8 items
__global__ void scan_kernel() {
    __shared__ int warp_sums[32];
    __shared__ int s_carry;
    int tid = threadIdx.x;
    int lane = tid & 31, wid = tid >> 5;
    if (tid == 0) s_carry = 0;
    __syncthreads();
    const int CHUNK = 1024 * 8;
    for (int base = 0; base < N_NODES; base += CHUNK) {
        int idx0 = base + tid * 8;
        int v[8], pre[8];
        int run = 0;
#pragma unroll
        for (int k = 0; k < 8; k++) {
            int i = idx0 + k;
            v[k] = (i < N_NODES) ? g_cnt[i] : 0;
            run += v[k];
            pre[k] = run;                    // inclusive within thread
        }
        int tsum = run;
        int x = tsum;
#pragma unroll
        for (int dsh = 1; dsh < 32; dsh <<= 1) {
            int y = __shfl_up_sync(0xffffffffu, x, dsh);
            if (lane >= dsh) x += y;
        }
        if (lane == 31) warp_sums[wid] = x;
        __syncthreads();
        if (wid == 0) {
            int w = warp_sums[lane];
#pragma unroll
            for (int dsh = 1; dsh < 32; dsh <<= 1) {
                int y = __shfl_up_sync(0xffffffffu, w, dsh);
                if (lane >= dsh) w += y;
            }
            warp_sums[lane] = w;
        }
        __syncthreads();
        int carry = s_carry;
        int off = carry + (wid > 0 ? warp_sums[wid - 1] : 0) + (x - tsum);
#pragma unroll
        for (int k = 0; k < 8; k++) {
            int i = idx0 + k;
            if (i < N_NODES) {
                int ex = off + (pre[k] - v[k]);  // exclusive prefix
                g_rowptr[i] = ex;
                g_fill[i] = ex;
            }
        }
        __syncthreads();
        if (tid == 0) s_carry = carry + warp_sums[31];
        __syncthreads();
    }
    if (threadIdx.x == 0) g_rowptr[N_NODES] = s_carry;  // == N_EDGES
}

__global__ void fill_kernel(const int* __restrict__ ei) {
    int e = blockIdx.x * 256 + threadIdx.x;
    if (e < N_EDGES) {
        int d = ei[e];
        int s = ei[N_EDGES + e];            // src = edge_index[1][e]
        int pos = atomicAdd(&g_fill[d], 1);
        g_col[pos] = s;
    }
}

// ---------------- column sum of input x (readout for layer 0) ----------------
__global__ void __launch_bounds__(256) colsum_kernel(const float4* __restrict__ in) {
    __shared__ float s[D];
    int fg = threadIdx.x & 31;
    int t = blockIdx.x * 256 + threadIdx.x;
    int stride = gridDim.x * 256;
    float4 ls = make_float4(0.f, 0.f, 0.f, 0.f);
    for (int idx = t; idx < N_NODES * F4; idx += stride) {
        float4 v = in[idx];
        ls.x += v.x; ls.y += v.y; ls.z += v.z; ls.w += v.w;
    }
    if (threadIdx.x < D) s[threadIdx.x] = 0.f;
    __syncthreads();
    int f = fg * 4;
    atomicAdd(&s[f + 0], ls.x);
    atomicAdd(&s[f + 1], ls.y);
    atomicAdd(&s[f + 2], ls.z);
    atomicAdd(&s[f + 3], ls.w);
    __syncthreads();
    if (threadIdx.x < D) atomicAdd(&g_ro[0][threadIdx.x], s[threadIdx.x]);
}

// ---------------- combine: h + CSR-gathered agg + readout; accumulate BN stats ----------------
__global__ void __launch_bounds__(256) combine_kernel(int layer, const float4* __restrict__ xin) {
    __shared__ float ssum[D], ssq[D];
    const float4* __restrict__ hin = (layer == 0) ? xin : (const float4*)g_h;
    int lane = threadIdx.x & 31;
    int gw = (blockIdx.x * 256 + threadIdx.x) >> 5;
    int nw = (gridDim.x * 256) >> 5;
    float4 ro = ((const float4*)&g_ro[layer][0])[lane];
    float4 ls = make_float4(0.f, 0.f, 0.f, 0.f);
    float4 lq = make_float4(0.f, 0.f, 0.f, 0.f);
    for (int i = gw; i < N_NODES; i += nw) {
        int beg = g_rowptr[i];
        int end = g_rowptr[i + 1];
        float4 a = hin[i * F4 + lane];
        int e = beg;
        for (; e + 1 < end; e += 2) {
            int j0 = g_col[e];
            int j1 = g_col[e + 1];
            float4 v0 = hin[j0 * F4 + lane];
            float4 v1 = hin[j1 * F4 + lane];
            a.x += v0.x; a.y += v0.y; a.z += v0.z; a.w += v0.w;
            a.x += v1.x; a.y += v1.y; a.z += v1.z; a.w += v1.w;
        }
        if (e < end) {
            int j = g_col[e];
            float4 v = hin[j * F4 + lane];
            a.x += v.x; a.y += v.y; a.z += v.z; a.w += v.w;
        }
        // stats on pre-readout values (avoids fp32 cancellation; var is shift-invariant)
        ls.x += a.x; ls.y += a.y; ls.z += a.z; ls.w += a.w;
        lq.x += a.x * a.x; lq.y += a.y * a.y; lq.z += a.z * a.z; lq.w += a.w * a.w;
        float4 tt;
        tt.x = a.x + ro.x; tt.y = a.y + ro.y; tt.z = a.z + ro.z; tt.w = a.w + ro.w;
        g_tmp[i * F4 + lane] = tt;
    }
    if (threadIdx.x < D) { ssum[threadIdx.x] = 0.f; ssq[threadIdx.x] = 0.f; }
    __syncthreads();
    int f = lane * 4;
    atomicAdd(&ssum[f + 0], ls.x); atomicAdd(&ssum[f + 1], ls.y);
    atomicAdd(&ssum[f + 2], ls.z); atomicAdd(&ssum[f + 3], ls.w);
    atomicAdd(&ssq[f + 0], lq.x);  atomicAdd(&ssq[f + 1], lq.y);
    atomicAdd(&ssq[f + 2], lq.z);  atomicAdd(&ssq[f + 3], lq.w);
    __syncthreads();
    if (threadIdx.x < D) {
        atomicAdd(&g_sum[layer][threadIdx.x], ssum[threadIdx.x]);
        atomicAdd(&g_sq[layer][threadIdx.x], ssq[threadIdx.x]);
    }
}

// ---------------- BN finalize: per-feature scale / mean / beta ----------------
__global__ void finalize_kernel(int layer, const float* __restrict__ gamma,
                                const float* __restrict__ beta) {
    int f = threadIdx.x;
    const float inv = 1.0f / (float)N_NODES;
    float mu = g_sum[layer][f] * inv;                       // mean of pre-readout values
    float var = g_sq[layer][f] * inv - mu * mu;             // shift-invariant variance
    g_scale[layer][f] = gamma[f] * rsqrtf(var + BN_EPS);
    g_mean[layer][f] = g_ro[layer][f] + mu;                 // mean of stored tmp values
    g_beta[layer][f] = beta[f];
}

// ---------------- normalize + relu: (tmp - mean)*scale + beta ; accumulate next readout ----------------
__global__ void __launch_bounds__(256) normalize_kernel(int layer) {
    __shared__ float s[D];
    int fg = threadIdx.x & 31;
    int t = blockIdx.x * 256 + threadIdx.x;
    int stride = gridDim.x * 256;
    float4 sc = ((const float4*)&g_scale[layer][0])[fg];
    float4 mn = ((const float4*)&g_mean[layer][0])[fg];
    float4 bt = ((const float4*)&g_beta[layer][0])[fg];
    float4 ls = make_float4(0.f, 0.f, 0.f, 0.f);
    for (int idx = t; idx < N_NODES * F4; idx += stride) {
        float4 v = g_tmp[idx];
        v.x = fmaxf(fmaf(v.x - mn.x, sc.x, bt.x), 0.f);
        v.y = fmaxf(fmaf(v.y - mn.y, sc.y, bt.y), 0.f);
        v.z = fmaxf(fmaf(v.z - mn.z, sc.z, bt.z), 0.f);
        v.w = fmaxf(fmaf(v.w - mn.w, sc.w, bt.w), 0.f);
        g_h[idx] = v;
        ls.x += v.x; ls.y += v.y; ls.z += v.z; ls.w += v.w;
    }
    if (threadIdx.x < D) s[threadIdx.x] = 0.f;
    __syncthreads();
    int f = fg * 4;
    atomicAdd(&s[f + 0], ls.x);
    atomicAdd(&s[f + 1], ls.y);
    atomicAdd(&s[f + 2], ls.z);
    atomicAdd(&s[f + 3], ls.w);
    __syncthreads();
    if (threadIdx.x < D) atomicAdd(&g_ro[layer + 1][threadIdx.x], s[threadIdx.x]);
}

// ---------------- final: fused (normalize+relu of layer2) @ W + b ----------------
// block: 256 threads, tile 128 rows x 64 cols; thread computes 8 rows x 4 cols
__global__ void __launch_bounds__(256) gemm_kernel(const float* __restrict__ W,
                                                   const float* __restrict__ b,
                                                   float4* __restrict__ out) {
    __shared__ float As[128 * 36];  // 128 rows x 32 k (+4 pad)
    __shared__ float Ws[32 * 68];   // 32 k x 64 cols (+4 pad)
    int tid = threadIdx.x;
    int row0 = blockIdx.x * 128;
    int cg = tid & 15;    // column group: cols cg*4 .. cg*4+3
    int rg = tid >> 4;    // row group: rows rg + 16*j
    const float4* W4 = (const float4*)W;
    const float4* sc4 = (const float4*)&g_scale[2][0];
    const float4* mn4 = (const float4*)&g_mean[2][0];
    const float4* bt4 = (const float4*)&g_beta[2][0];
    float4 acc[8];
#pragma unroll
    for (int j = 0; j < 8; j++) acc[j] = make_float4(0.f, 0.f, 0.f, 0.f);

    for (int kk = 0; kk < 4; kk++) {
        // stage A chunk with fused (x-mean)*scale+beta, relu
#pragma unroll
        for (int it = 0; it < 4; it++) {
            int lin = tid + it * 256;
            int r = lin >> 3;
            int kc = lin & 7;
            int grow = row0 + r;
            float4 a = (grow < N_NODES) ? g_tmp[grow * F4 + kk * 8 + kc]
                                        : make_float4(0.f, 0.f, 0.f, 0.f);
            float4 s = sc4[kk * 8 + kc];
            float4 m = mn4[kk * 8 + kc];
            float4 t = bt4[kk * 8 + kc];
            a.x = fmaxf(fmaf(a.x - m.x, s.x, t.x), 0.f);
            a.y = fmaxf(fmaf(a.y - m.y, s.y, t.y), 0.f);
            a.z = fmaxf(fmaf(a.z - m.z, s.z, t.z), 0.f);
            a.w = fmaxf(fmaf(a.w - m.w, s.w, t.w), 0.f);
            *(float4*)&As[r * 36 + kc * 4] = a;
        }
        // stage W chunk
#pragma unroll
        for (int it = 0; it < 2; it++) {
            int lin = tid + it * 256;
            int k = lin >> 4;
            int c4 = lin & 15;
            *(float4*)&Ws[k * 68 + c4 * 4] = W4[(kk * 32 + k) * 16 + c4];
        }
        __syncthreads();
#pragma unroll
        for (int k4 = 0; k4 < 8; k4++) {
            float4 w0 = *(const float4*)&Ws[(k4 * 4 + 0) * 68 + cg * 4];
            float4 w1 = *(const float4*)&Ws[(k4 * 4 + 1) * 68 + cg * 4];
            float4 w2 = *(const float4*)&Ws[(k4 * 4 + 2) * 68 + cg * 4];
            float4 w3 = *(const float4*)&Ws[(k4 * 4 + 3) * 68 + cg * 4];
#pragma unroll
            for (int j = 0; j < 8; j++) {
                float4 a = *(const float4*)&As[(rg + 16 * j) * 36 + k4 * 4];
                acc[j].x = fmaf(a.x, w0.x, fmaf(a.y, w1.x, fmaf(a.z, w2.x, fmaf(a.w, w3.x, acc[j].x))));
                acc[j].y = fmaf(a.x, w0.y, fmaf(a.y, w1.y, fmaf(a.z, w2.y, fmaf(a.w, w3.y, acc[j].y))));
                acc[j].z = fmaf(a.x, w0.z, fmaf(a.y, w1.z, fmaf(a.z, w2.z, fmaf(a.w, w3.z, acc[j].z))));
                acc[j].w = fmaf(a.x, w0.w, fmaf(a.y, w1.w, fmaf(a.z, w2.w, fmaf(a.w, w3.w, acc[j].w))));
            }
        }
        __syncthreads();
    }
    float4 bb = ((const float4*)b)[cg];
#pragma unroll
    for (int j = 0; j < 8; j++) {
        int grow = row0 + rg + 16 * j;
        if (grow < N_NODES) {
            float4 o;
            o.x = acc[j].x + bb.x;
            o.y = acc[j].y + bb.y;
            o.z = acc[j].z + bb.z;
            o.w = acc[j].w + bb.w;
            out[grow * 16 + cg] = o;
        }
    }
}

// ---------------- launch ----------------
extern "C" void kernel_launch(void* const* d_in, const int* in_sizes, int n_in,
                              void* d_out, int out_size) {
    (void)in_sizes; (void)n_in; (void)out_size;
    const float* x = (const float*)d_in[0];
    const int* ei = (const int*)d_in[1];      // int32 per harness dtype table
    const float* gamma = (const float*)d_in[2];
    const float* beta = (const float*)d_in[3];
    const float* W = (const float*)d_in[4];
    const float* b = (const float*)d_in[5];
    float4* out = (float4*)d_out;

    const int WIDE = 1184;  // 8 * 148 SMs

    zero_kernel<<<(N_NODES + 255) / 256, 256>>>();
    hist_kernel<<<(N_EDGES + 255) / 256, 256>>>(ei);
    scan_kernel<<<1, 1024>>>();
    fill_kernel<<<(N_EDGES + 255) / 256, 256>>>(ei);
    colsum_kernel<<<WIDE, 256>>>((const float4*)x);

    for (int layer = 0; layer < 3; layer++) {
        combine_kernel<<<WIDE, 256>>>(layer, (const float4*)x);
        finalize_kernel<<<1, D>>>(layer, gamma + layer * D, beta + layer * D);
        if (layer < 2) normalize_kernel<<<WIDE, 256>>>(layer);
    }
    gemm_kernel<<<(N_NODES + 127) / 128, 256>>>(W, b, out);
}